// round 15
// baseline (speedup 1.0000x reference)
#include <cuda_runtime.h>
#include <cuda_bf16.h>
#include <math.h>
#include <stdint.h>

#define S_TOK 4096
#define M_DIM 1024
#define H_DIM 4096
#define E_NUM 8
#define C_CAP 1024
#define KTOP  2

// ---------------- scratch (__device__ globals; referenced ONLY from device code) ----------------
__device__ float d_xr[(size_t)S_TOK * M_DIM];                 // tf32-rounded x
__device__ float d_h[(size_t)E_NUM * C_CAP * H_DIM];          // tf32-rounded activations
__device__ float d_yo[(size_t)E_NUM * C_CAP * M_DIM];
__device__ float d_scores[S_TOK * E_NUM];
__device__ int   d_topk[S_TOK * KTOP];
__device__ float d_gate[S_TOK * KTOP];
__device__ int   d_flat[S_TOK * KTOP];
__device__ int   d_perm[E_NUM * C_CAP];
__device__ float d_me[E_NUM];
__device__ int   d_ce[E_NUM];

__device__ const float* g_x;
__device__ const float* g_wg;
__device__ const float* g_fc1w;
__device__ const float* g_fc1b;
__device__ const float* g_fc2w;
__device__ const float* g_fc2b;

// ---------------- generic-PTX helpers (sm_80+; valid on compute_103) ----------------
__device__ __forceinline__ uint32_t smem_u32(const void* p) {
    uint32_t a;
    asm("{ .reg .u64 t; cvta.to.shared.u64 t, %1; cvt.u32.u64 %0, t; }" : "=r"(a) : "l"(p));
    return a;
}
__device__ __forceinline__ void cpa16(uint32_t dst, const void* src, int src_bytes) {
    asm volatile("cp.async.cg.shared.global [%0], [%1], 16, %2;"
                 :: "r"(dst), "l"(src), "r"(src_bytes) : "memory");
}
#define CP_COMMIT() asm volatile("cp.async.commit_group;" ::: "memory")
#define CP_WAIT(n)  asm volatile("cp.async.wait_group %0;" :: "n"(n) : "memory")
#define LDSM4(r0, r1, r2, r3, addr)                                        \
    asm volatile("ldmatrix.sync.aligned.m8n8.x4.shared.b16 {%0,%1,%2,%3}, [%4];" \
                 : "=r"(r0), "=r"(r1), "=r"(r2), "=r"(r3) : "r"(addr))
#define MMA16808(d, a, b0, b1)                                             \
    asm volatile("mma.sync.aligned.m16n8k8.row.col.f32.tf32.tf32.f32 "     \
                 "{%0,%1,%2,%3}, {%4,%5,%6,%7}, {%8,%9}, {%0,%1,%2,%3};"   \
                 : "+f"((d)[0]), "+f"((d)[1]), "+f"((d)[2]), "+f"((d)[3])  \
                 : "r"((a)[0]), "r"((a)[1]), "r"((a)[2]), "r"((a)[3]),     \
                   "r"(b0), "r"(b1))
__device__ __forceinline__ uint32_t to_tf32(float v) {
    uint32_t r;
    asm("cvt.rna.tf32.f32 %0, %1;" : "=r"(r) : "f"(v));
    return r;
}
__device__ __forceinline__ uint32_t lds_tf32(uint32_t addr) {
    float v;
    asm volatile("ld.shared.f32 %0, [%1];" : "=f"(v) : "r"(addr));
    return to_tf32(v);
}

// ---------------- select: resolve ambiguous inputs by content ----------------
__global__ __launch_bounds__(32) void select_kernel(
    const float* x, const float* fc1b,
    const float* s0, const float* s1,
    const float* b0, const float* b1) {
    int lane = threadIdx.x;
    float sa = 0.f, sb = 0.f, ca = 0.f, cb = 0.f;
    for (int i = lane; i < 8192; i += 32) {
        sa += fabsf(s0[i]);
        sb += fabsf(s1[i]);
        ca += fabsf(b0[i]);
        cb += fabsf(b1[i]);
    }
    #pragma unroll
    for (int off = 16; off; off >>= 1) {
        sa += __shfl_down_sync(0xffffffffu, sa, off);
        sb += __shfl_down_sync(0xffffffffu, sb, off);
        ca += __shfl_down_sync(0xffffffffu, ca, off);
        cb += __shfl_down_sync(0xffffffffu, cb, off);
    }
    if (lane == 0) {
        g_x = x;
        g_fc1b = fc1b;
        if (sa >= sb) { g_wg = s0; g_fc2b = s1; }
        else          { g_wg = s1; g_fc2b = s0; }
        if (ca >= cb) { g_fc1w = b0; g_fc2w = b1; }
        else          { g_fc1w = b1; g_fc2w = b0; }
        for (int e = 0; e < E_NUM; e++) d_ce[e] = 0;
    }
}

// ------- gating + x rounding fused: one warp per token; float4 loads; writes d_xr -------
__global__ __launch_bounds__(256) void gate_kernel() {
    const int warp = threadIdx.x >> 5;
    const int lane = threadIdx.x & 31;
    const int s = blockIdx.x * 8 + warp;
    if (s >= S_TOK) return;
    const float* x = g_x;
    const float* wg = g_wg;

    float acc[E_NUM] = {0.f, 0.f, 0.f, 0.f, 0.f, 0.f, 0.f, 0.f};
    const float4* xr4 = (const float4*)(x + (size_t)s * M_DIM);
    uint4* dr4 = (uint4*)(d_xr + (size_t)s * M_DIM);
    #pragma unroll 2
    for (int i = 0; i < 8; i++) {
        int k4 = lane + i * 32;            // float4 index within row (0..255)
        float4 v = xr4[k4];
        uint4 o;
        o.x = to_tf32(v.x);
        o.y = to_tf32(v.y);
        o.z = to_tf32(v.z);
        o.w = to_tf32(v.w);
        dr4[k4] = o;
        float xv4[4] = {v.x, v.y, v.z, v.w};
        const float4* w = (const float4*)(wg + (size_t)(k4 * 4) * E_NUM);
        #pragma unroll
        for (int j = 0; j < 4; j++) {
            float xv = xv4[j];
            float4 w0 = w[j * 2], w1 = w[j * 2 + 1];
            acc[0] += xv * w0.x; acc[1] += xv * w0.y; acc[2] += xv * w0.z; acc[3] += xv * w0.w;
            acc[4] += xv * w1.x; acc[5] += xv * w1.y; acc[6] += xv * w1.z; acc[7] += xv * w1.w;
        }
    }
    #pragma unroll
    for (int off = 16; off; off >>= 1) {
        #pragma unroll
        for (int e = 0; e < E_NUM; e++)
            acc[e] += __shfl_down_sync(0xffffffffu, acc[e], off);
    }
    if (lane == 0) {
        float mx = acc[0];
        #pragma unroll
        for (int e = 1; e < E_NUM; e++) mx = fmaxf(mx, acc[e]);
        float sum = 0.f, sc[E_NUM];
        #pragma unroll
        for (int e = 0; e < E_NUM; e++) { sc[e] = expf(acc[e] - mx); sum += sc[e]; }
        float inv = 1.f / sum;
        #pragma unroll
        for (int e = 0; e < E_NUM; e++) { sc[e] *= inv; d_scores[s * E_NUM + e] = sc[e]; }
        int id0 = 0;
        #pragma unroll
        for (int e = 1; e < E_NUM; e++) if (sc[e] > sc[id0]) id0 = e;
        int id1 = -1;
        float b1 = -1.f;
        #pragma unroll
        for (int e = 0; e < E_NUM; e++) {
            if (e != id0 && sc[e] > b1) { b1 = sc[e]; id1 = e; }
        }
        if (id1 < 0) id1 = (id0 + 1) & 7;
        float v0 = sc[id0], v1 = sc[id1];
        float denom = fmaxf(v0 + v1, 1e-7f);
        d_topk[s * 2 + 0] = id0;
        d_topk[s * 2 + 1] = id1;
        d_gate[s * 2 + 0] = v0 / denom;
        d_gate[s * 2 + 1] = v1 / denom;
        atomicAdd(&d_ce[id0], 1);
    }
}

// ---- routing (two-level scan) + me reduction fused; token-ordered, deterministic ----
#define NCHUNK 128   // 4096 tokens / 32 per chunk
__global__ __launch_bounds__(256) void route_kernel() {
    const int tid = threadIdx.x;
    const int lane = tid & 31;
    const int wid = tid >> 5;
    __shared__ int stopk[S_TOK * KTOP];              // 32 KB
    __shared__ int scnt[KTOP][E_NUM][NCHUNK];        // 8 KB
    __shared__ int sbase[KTOP][E_NUM][NCHUNK];       // 8 KB

    for (int i = tid; i < E_NUM * C_CAP; i += 256) d_perm[i] = -1;
    for (int i = tid; i < S_TOK * KTOP; i += 256) stopk[i] = d_topk[i];
    __syncthreads();

    const int p = tid >> 7;           // phase 0/1
    const int chunk = tid & 127;      // 32-token chunk
    // Stage 1: per-(phase, chunk) expert histogram
    {
        int cnt[E_NUM];
        #pragma unroll
        for (int e = 0; e < E_NUM; e++) cnt[e] = 0;
        #pragma unroll 4
        for (int j = 0; j < 32; j++) {
            int e = stopk[(chunk * 32 + j) * 2 + p];
            e = (e < 0) ? 0 : ((e > 7) ? 7 : e);
            #pragma unroll
            for (int ee = 0; ee < E_NUM; ee++) cnt[ee] += (e == ee);
        }
        #pragma unroll
        for (int e = 0; e < E_NUM; e++) scnt[p][e][chunk] = cnt[e];
    }
    __syncthreads();

    // Stage 2: per-expert exclusive prefix over 256 phase-major positions (warp w = expert w)
    {
        const int e = wid;
        int v[8], pre[8], run = 0;
        #pragma unroll
        for (int j = 0; j < 8; j++) {
            int idx = lane * 8 + j;           // 0..255, phase-major
            v[j] = scnt[idx >> 7][e][idx & 127];
            pre[j] = run;
            run += v[j];
        }
        int lb = run;
        #pragma unroll
        for (int off = 1; off < 32; off <<= 1) {
            int t = __shfl_up_sync(0xffffffffu, lb, off);
            if (lane >= off) lb += t;
        }
        lb -= run;                             // exclusive
        #pragma unroll
        for (int j = 0; j < 8; j++) {
            int idx = lane * 8 + j;
            sbase[idx >> 7][e][idx & 127] = lb + pre[j];
        }
    }
    __syncthreads();

    // Stage 3: placement (parallel across all 256 (phase,chunk) threads)
    {
        int run[E_NUM];
        #pragma unroll
        for (int e = 0; e < E_NUM; e++) run[e] = 0;
        #pragma unroll 4
        for (int j = 0; j < 32; j++) {
            int s = chunk * 32 + j;
            int e = stopk[s * 2 + p];
            e = (e < 0) ? 0 : ((e > 7) ? 7 : e);
            int r = 0;
            #pragma unroll
            for (int ee = 0; ee < E_NUM; ee++) {
                if (e == ee) r = run[ee]++;
            }
            int loc = sbase[p][e][chunk] + r;
            bool valid = loc < C_CAP;
            int flat = e * C_CAP + (valid ? loc : (C_CAP - 1));
            d_flat[s * 2 + p] = flat;
            if (valid) d_perm[flat] = s;
            else       d_gate[s * 2 + p] = 0.f;
        }
    }

    // Stage 4: me[e] = sum_s scores[s][e] — warp w owns expert w, fixed-order reduce
    {
        const int e = wid;
        float acc = 0.f;
        for (int s = lane; s < S_TOK; s += 32)
            acc += d_scores[s * E_NUM + e];
        #pragma unroll
        for (int off = 16; off; off >>= 1)
            acc += __shfl_down_sync(0xffffffffu, acc, off);
        if (lane == 0) d_me[e] = acc;
    }
}

// -------- tf32 GEMM, block 128x256, 256 threads / 8 warps (warp 64x64), 4-stage cp.async --------
// A: [m][k] K-major smem (144B rows), PRE-ROUNDED tf32 (d_xr / d_h) -> clean ldsm->MMA chain.
// B: [k][n] smem direct from original weights; fragments via 2 conflict-free LDS + cvt.rna.
#define ROWB_A 144
#define ROWN_B 1056
#define OFF_B  18432              // 128 * 144
#define STAGE_B 52224             // 18432 + 32*1056
#define NSTAGE 4
template <int PHASE>
__global__ __launch_bounds__(256) void gemm_mma() {
    constexpr int KSEG = (PHASE == 1) ? M_DIM : H_DIM;
    constexpr int NDIM = (PHASE == 1) ? H_DIM : M_DIM;
    constexpr int TPS = KSEG / 32;

    extern __shared__ __align__(16) char smem[];
    __shared__ int sRow[128];

    const int tid = threadIdx.x;
    const int lane = tid & 31;
    const int wid = tid >> 5;
    const int wm = wid >> 2;        // 0..1  (64-row slice)
    const int wn = wid & 3;         // 0..3  (64-col slice)
    const int e = blockIdx.z;
    const int M0 = blockIdx.y * 128;
    const int N0 = blockIdx.x * 256;
    const uint32_t sbase = smem_u32(smem);

    if (PHASE == 1) {
        if (tid < 128) sRow[tid] = d_perm[e * C_CAP + tid + M0];
    }
    __syncthreads();

    const float* A = (PHASE == 1) ? d_xr : d_h;        // pre-rounded tf32
    const float* W = (PHASE == 1) ? g_fc1w : g_fc2w;   // [e][k][n], raw fp32

    auto issue_stage = [&](int stg, int kt) {
        const int kb = kt * 32;
        uint32_t base = sbase + stg * STAGE_B;
        #pragma unroll
        for (int i = 0; i < 4; i++) {       // A: 128 rows x 8 chunks(16B)
            int ch = tid + i * 256, r = ch >> 3, c = ch & 7;
            size_t srcoff;
            int bytes = 16;
            if (PHASE == 1) {
                int sr = sRow[r];
                srcoff = (sr >= 0) ? ((size_t)sr * KSEG + kb + c * 4) : 0;
                if (sr < 0) bytes = 0;
            } else {
                srcoff = (size_t)(e * C_CAP + M0 + r) * KSEG + kb + c * 4;
            }
            cpa16(base + r * ROWB_A + c * 16, A + srcoff, bytes);
        }
        #pragma unroll
        for (int i = 0; i < 8; i++) {       // B: 32 k-rows x 64 chunks(16B)
            int ch = tid + i * 256, r = ch >> 6, c = ch & 63;
            size_t srcoff = (size_t)e * KSEG * NDIM + (size_t)(kb + r) * NDIM + N0 + c * 4;
            cpa16(base + OFF_B + r * ROWN_B + c * 16, W + srcoff, 16);
        }
    };

    float acc[4][8][4];
    #pragma unroll
    for (int mi = 0; mi < 4; mi++)
        #pragma unroll
        for (int ni = 0; ni < 8; ni++)
            #pragma unroll
            for (int q = 0; q < 4; q++) acc[mi][ni][q] = 0.f;

    const int l_r = lane & 15;
    const int l_c = (lane >> 4) * 16;
    const int bq = lane >> 2;       // n offset within n8 block
    const int br = lane & 3;        // k offset within k8 block

    issue_stage(0, 0);
    CP_COMMIT();
    issue_stage(1, 1);
    CP_COMMIT();
    issue_stage(2, 2);
    CP_COMMIT();

    for (int it = 0; it < TPS; it++) {
        // ensure stage it's group is complete (exact outstanding counts)
        if (it + 3 < TPS)      CP_WAIT(3);
        else if (it + 2 < TPS) CP_WAIT(2);
        else if (it + 1 < TPS) CP_WAIT(1);
        else                   CP_WAIT(0);
        __syncthreads();  // single barrier per iter; stage (it+3)%4 was last read at it-1

        if (it + 3 < TPS) { issue_stage((it + 3) % NSTAGE, it + 3); CP_COMMIT(); }

        uint32_t base = sbase + (it % NSTAGE) * STAGE_B;
        #pragma unroll
        for (int kk = 0; kk < 4; kk++) {    // four k8 steps per k32 stage
            uint32_t af[4][4];
            #pragma unroll
            for (int mi = 0; mi < 4; mi++) {
                uint32_t ad = base + (uint32_t)(wm * 64 + mi * 16 + l_r) * ROWB_A
                            + (uint32_t)(kk * 32 + l_c);
                LDSM4(af[mi][0], af[mi][1], af[mi][2], af[mi][3], ad);
            }
            uint32_t bd0 = base + OFF_B + (uint32_t)(kk * 8 + br) * ROWN_B
                         + (uint32_t)(wn * 64 + bq) * 4;
            uint32_t bfr[8][2];
            #pragma unroll
            for (int ni = 0; ni < 8; ni++) {
                bfr[ni][0] = lds_tf32(bd0 + ni * 32);
                bfr[ni][1] = lds_tf32(bd0 + ni * 32 + 4 * ROWN_B);
            }
            #pragma unroll
            for (int mi = 0; mi < 4; mi++)
                #pragma unroll
                for (int ni = 0; ni < 8; ni++)
                    MMA16808(acc[mi][ni], af[mi], bfr[ni][0], bfr[ni][1]);
        }
    }

    // ---- epilogue ----
    const float* bias = (PHASE == 1) ? g_fc1b : g_fc2b;
    #pragma unroll
    for (int mi = 0; mi < 4; mi++) {
        #pragma unroll
        for (int ni = 0; ni < 8; ni++) {
            int c = N0 + wn * 64 + ni * 8 + (lane & 3) * 2;
            float2 bv = *(const float2*)&bias[(size_t)e * NDIM + c];
            int r0 = M0 + wm * 64 + mi * 16 + (lane >> 2);
            #pragma unroll
            for (int h = 0; h < 2; h++) {
                int rg = r0 + h * 8;
                float v0 = acc[mi][ni][h * 2 + 0] + bv.x;
                float v1 = acc[mi][ni][h * 2 + 1] + bv.y;
                if (PHASE == 1) {
                    v0 = fmaxf(v0, 0.f);
                    v1 = fmaxf(v1, 0.f);
                    uint2 t = make_uint2(to_tf32(v0), to_tf32(v1));
                    size_t o = (size_t)(e * C_CAP + rg) * H_DIM + c;
                    *(uint2*)(d_h + o) = t;
                } else {
                    size_t o = (size_t)(e * C_CAP + rg) * M_DIM + c;
                    *(float2*)(d_yo + o) = make_float2(v0, v1);
                }
            }
        }
    }
}

// ---------------- combine ----------------
__global__ __launch_bounds__(256) void combine_kernel(float* __restrict__ out) {
    int s = blockIdx.x;
    int tid = threadIdx.x;
    int f0 = d_flat[s * 2 + 0];
    int f1 = d_flat[s * 2 + 1];
    float g0 = d_gate[s * 2 + 0];
    float g1 = d_gate[s * 2 + 1];
    float4 a = ((const float4*)(d_yo + (size_t)f0 * M_DIM))[tid];
    float4 b = ((const float4*)(d_yo + (size_t)f1 * M_DIM))[tid];
    float4 o;
    o.x = g0 * a.x + g1 * b.x;
    o.y = g0 * a.y + g1 * b.y;
    o.z = g0 * a.z + g1 * b.z;
    o.w = g0 * a.w + g1 * b.w;
    ((float4*)(out + (size_t)s * M_DIM))[tid] = o;
}

// ---------------- l_aux ----------------
__global__ __launch_bounds__(32) void laux_kernel(float* __restrict__ out, int write) {
    if (threadIdx.x == 0 && write) {
        float l = 0.f;
        for (int e = 0; e < E_NUM; e++)
            l += (d_me[e] / (float)S_TOK) * ((float)d_ce[e] / (float)S_TOK);
        out[(size_t)S_TOK * M_DIM] = l * (float)E_NUM;
    }
}

// ---------------- launch ----------------
extern "C" void kernel_launch(void* const* d_in, const int* in_sizes, int n_in,
                              void* d_out, int out_size) {
    long long mx = 0;
    for (int i = 0; i < n_in; i++) if ((long long)in_sizes[i] > mx) mx = in_sizes[i];
    long long div = (mx >= 134217728LL) ? 4 : 1;

    const float *x = 0, *fc1_b = 0;
    const float* big[2] = {0, 0};
    const float* sml[2] = {0, 0};
    int nbig = 0, nsml = 0;
    for (int i = 0; i < n_in; i++) {
        const float* p = (const float*)d_in[i];
        long long n = (long long)in_sizes[i] / div;
        if (n == (long long)S_TOK * M_DIM) x = p;
        else if (n == (long long)E_NUM * H_DIM) fc1_b = p;
        else if (n == (long long)E_NUM * M_DIM * H_DIM) { if (nbig < 2) big[nbig++] = p; }
        else if (n == (long long)M_DIM * E_NUM) { if (nsml < 2) sml[nsml++] = p; }
    }
    if (!x || !fc1_b || nbig < 2 || nsml < 2) {
        x = (const float*)d_in[0];
        sml[0] = (const float*)d_in[1];
        big[0] = (const float*)d_in[2];
        fc1_b = (const float*)d_in[3];
        big[1] = (const float*)d_in[4];
        sml[1] = (const float*)d_in[5];
    }
    float* out = (float*)d_out;

    const int SMEM_DYN = NSTAGE * STAGE_B;  // 208896 B
    cudaFuncSetAttribute(gemm_mma<1>, cudaFuncAttributeMaxDynamicSharedMemorySize, SMEM_DYN);
    cudaFuncSetAttribute(gemm_mma<2>, cudaFuncAttributeMaxDynamicSharedMemorySize, SMEM_DYN);

    select_kernel<<<1, 32>>>(x, fc1_b, sml[0], sml[1], big[0], big[1]);
    gate_kernel<<<S_TOK / 8, 256>>>();   // also writes d_xr (fused rounding)
    route_kernel<<<1, 256>>>();          // also computes d_me (fused)

    {
        dim3 g(H_DIM / 256, C_CAP / 128, E_NUM);  // (16, 8, 8)
        gemm_mma<1><<<g, 256, SMEM_DYN>>>();
    }
    {
        dim3 g(M_DIM / 256, C_CAP / 128, E_NUM);  // (4, 8, 8)
        gemm_mma<2><<<g, 256, SMEM_DYN>>>();
    }

    combine_kernel<<<S_TOK, 256>>>(out);
    laux_kernel<<<1, 32>>>(out, out_size > S_TOK * M_DIM ? 1 : 0);
}

// round 16
// speedup vs baseline: 1.0454x; 1.0454x over previous
#include <cuda_runtime.h>
#include <cuda_bf16.h>
#include <math.h>
#include <stdint.h>

#define S_TOK 4096
#define M_DIM 1024
#define H_DIM 4096
#define E_NUM 8
#define C_CAP 1024
#define KTOP  2

// ---------------- scratch (__device__ globals; referenced ONLY from device code) ----------------
__device__ float d_xr[(size_t)S_TOK * M_DIM];                 // tf32-rounded x
__device__ float d_h[(size_t)E_NUM * C_CAP * H_DIM];          // tf32-rounded activations
__device__ float d_yo[(size_t)E_NUM * C_CAP * M_DIM];
__device__ float d_scores[S_TOK * E_NUM];
__device__ int   d_topk[S_TOK * KTOP];
__device__ float d_gate[S_TOK * KTOP];
__device__ int   d_flat[S_TOK * KTOP];
__device__ int   d_perm[E_NUM * C_CAP];
__device__ float d_me[E_NUM];
__device__ int   d_ce[E_NUM];

__device__ const float* g_x;
__device__ const float* g_wg;
__device__ const float* g_fc1w;
__device__ const float* g_fc1b;
__device__ const float* g_fc2w;
__device__ const float* g_fc2b;

// ---------------- generic-PTX helpers (sm_80+; valid on compute_103) ----------------
__device__ __forceinline__ uint32_t smem_u32(const void* p) {
    uint32_t a;
    asm("{ .reg .u64 t; cvta.to.shared.u64 t, %1; cvt.u32.u64 %0, t; }" : "=r"(a) : "l"(p));
    return a;
}
__device__ __forceinline__ void cpa16(uint32_t dst, const void* src, int src_bytes) {
    asm volatile("cp.async.cg.shared.global [%0], [%1], 16, %2;"
                 :: "r"(dst), "l"(src), "r"(src_bytes) : "memory");
}
#define CP_COMMIT() asm volatile("cp.async.commit_group;" ::: "memory")
#define CP_WAIT(n)  asm volatile("cp.async.wait_group %0;" :: "n"(n) : "memory")
#define LDSM4(r0, r1, r2, r3, addr)                                        \
    asm volatile("ldmatrix.sync.aligned.m8n8.x4.shared.b16 {%0,%1,%2,%3}, [%4];" \
                 : "=r"(r0), "=r"(r1), "=r"(r2), "=r"(r3) : "r"(addr))
#define MMA16808(d, a, b0, b1)                                             \
    asm volatile("mma.sync.aligned.m16n8k8.row.col.f32.tf32.tf32.f32 "     \
                 "{%0,%1,%2,%3}, {%4,%5,%6,%7}, {%8,%9}, {%0,%1,%2,%3};"   \
                 : "+f"((d)[0]), "+f"((d)[1]), "+f"((d)[2]), "+f"((d)[3])  \
                 : "r"((a)[0]), "r"((a)[1]), "r"((a)[2]), "r"((a)[3]),     \
                   "r"(b0), "r"(b1))
__device__ __forceinline__ uint32_t to_tf32(float v) {
    uint32_t r;
    asm("cvt.rna.tf32.f32 %0, %1;" : "=r"(r) : "f"(v));
    return r;
}
__device__ __forceinline__ uint32_t lds_tf32(uint32_t addr) {
    float v;
    asm volatile("ld.shared.f32 %0, [%1];" : "=f"(v) : "r"(addr));
    return to_tf32(v);
}

// ---------------- select: resolve ambiguous inputs by content ----------------
__global__ __launch_bounds__(32) void select_kernel(
    const float* x, const float* fc1b,
    const float* s0, const float* s1,
    const float* b0, const float* b1) {
    int lane = threadIdx.x;
    float sa = 0.f, sb = 0.f, ca = 0.f, cb = 0.f;
    for (int i = lane; i < 8192; i += 32) {
        sa += fabsf(s0[i]);
        sb += fabsf(s1[i]);
        ca += fabsf(b0[i]);
        cb += fabsf(b1[i]);
    }
    #pragma unroll
    for (int off = 16; off; off >>= 1) {
        sa += __shfl_down_sync(0xffffffffu, sa, off);
        sb += __shfl_down_sync(0xffffffffu, sb, off);
        ca += __shfl_down_sync(0xffffffffu, ca, off);
        cb += __shfl_down_sync(0xffffffffu, cb, off);
    }
    if (lane == 0) {
        g_x = x;
        g_fc1b = fc1b;
        if (sa >= sb) { g_wg = s0; g_fc2b = s1; }
        else          { g_wg = s1; g_fc2b = s0; }
        if (ca >= cb) { g_fc1w = b0; g_fc2w = b1; }
        else          { g_fc1w = b1; g_fc2w = b0; }
        for (int e = 0; e < E_NUM; e++) d_ce[e] = 0;
    }
}

// ---------------- round x to tf32 (vectorized) ----------------
__global__ __launch_bounds__(256) void round_x_kernel() {
    size_t i4 = (size_t)blockIdx.x * 256 + threadIdx.x;
    float4 v = ((const float4*)g_x)[i4];
    uint4 o;
    o.x = to_tf32(v.x);
    o.y = to_tf32(v.y);
    o.z = to_tf32(v.z);
    o.w = to_tf32(v.w);
    ((uint4*)d_xr)[i4] = o;
}

// ---------------- gating: one warp per token (R14 numerics, unchanged) ----------------
__global__ __launch_bounds__(256) void gate_kernel() {
    const int warp = threadIdx.x >> 5;
    const int lane = threadIdx.x & 31;
    const int s = blockIdx.x * 8 + warp;
    if (s >= S_TOK) return;
    const float* x = g_x;
    const float* wg = g_wg;

    float acc[E_NUM] = {0.f, 0.f, 0.f, 0.f, 0.f, 0.f, 0.f, 0.f};
    const float* xrow = x + (size_t)s * M_DIM;
    for (int k = lane; k < M_DIM; k += 32) {
        float xv = xrow[k];
        const float4* w = (const float4*)(wg + (size_t)k * E_NUM);
        float4 w0 = w[0], w1 = w[1];
        acc[0] += xv * w0.x; acc[1] += xv * w0.y; acc[2] += xv * w0.z; acc[3] += xv * w0.w;
        acc[4] += xv * w1.x; acc[5] += xv * w1.y; acc[6] += xv * w1.z; acc[7] += xv * w1.w;
    }
    #pragma unroll
    for (int off = 16; off; off >>= 1) {
        #pragma unroll
        for (int e = 0; e < E_NUM; e++)
            acc[e] += __shfl_down_sync(0xffffffffu, acc[e], off);
    }
    if (lane == 0) {
        float mx = acc[0];
        #pragma unroll
        for (int e = 1; e < E_NUM; e++) mx = fmaxf(mx, acc[e]);
        float sum = 0.f, sc[E_NUM];
        #pragma unroll
        for (int e = 0; e < E_NUM; e++) { sc[e] = expf(acc[e] - mx); sum += sc[e]; }
        float inv = 1.f / sum;
        #pragma unroll
        for (int e = 0; e < E_NUM; e++) { sc[e] *= inv; d_scores[s * E_NUM + e] = sc[e]; }
        int id0 = 0;
        #pragma unroll
        for (int e = 1; e < E_NUM; e++) if (sc[e] > sc[id0]) id0 = e;
        int id1 = -1;
        float b1 = -1.f;
        #pragma unroll
        for (int e = 0; e < E_NUM; e++) {
            if (e != id0 && sc[e] > b1) { b1 = sc[e]; id1 = e; }
        }
        if (id1 < 0) id1 = (id0 + 1) & 7;
        float v0 = sc[id0], v1 = sc[id1];
        float denom = fmaxf(v0 + v1, 1e-7f);
        d_topk[s * 2 + 0] = id0;
        d_topk[s * 2 + 1] = id1;
        d_gate[s * 2 + 0] = v0 / denom;
        d_gate[s * 2 + 1] = v1 / denom;
        atomicAdd(&d_ce[id0], 1);
    }
}

// ---- routing (two-level scan) + me reduction fused; token-ordered, deterministic ----
#define NCHUNK 128   // 4096 tokens / 32 per chunk
__global__ __launch_bounds__(256) void route_kernel() {
    const int tid = threadIdx.x;
    const int lane = tid & 31;
    const int wid = tid >> 5;
    __shared__ int stopk[S_TOK * KTOP];              // 32 KB
    __shared__ int scnt[KTOP][E_NUM][NCHUNK];        // 8 KB
    __shared__ int sbase[KTOP][E_NUM][NCHUNK];       // 8 KB

    for (int i = tid; i < E_NUM * C_CAP; i += 256) d_perm[i] = -1;
    for (int i = tid; i < S_TOK * KTOP; i += 256) stopk[i] = d_topk[i];
    __syncthreads();

    const int p = tid >> 7;           // phase 0/1
    const int chunk = tid & 127;      // 32-token chunk
    // Stage 1: per-(phase, chunk) expert histogram
    {
        int cnt[E_NUM];
        #pragma unroll
        for (int e = 0; e < E_NUM; e++) cnt[e] = 0;
        #pragma unroll 4
        for (int j = 0; j < 32; j++) {
            int e = stopk[(chunk * 32 + j) * 2 + p];
            e = (e < 0) ? 0 : ((e > 7) ? 7 : e);
            #pragma unroll
            for (int ee = 0; ee < E_NUM; ee++) cnt[ee] += (e == ee);
        }
        #pragma unroll
        for (int e = 0; e < E_NUM; e++) scnt[p][e][chunk] = cnt[e];
    }
    __syncthreads();

    // Stage 2: per-expert exclusive prefix over 256 phase-major positions (warp w = expert w)
    {
        const int e = wid;
        int v[8], pre[8], run = 0;
        #pragma unroll
        for (int j = 0; j < 8; j++) {
            int idx = lane * 8 + j;           // 0..255, phase-major
            v[j] = scnt[idx >> 7][e][idx & 127];
            pre[j] = run;
            run += v[j];
        }
        int lb = run;
        #pragma unroll
        for (int off = 1; off < 32; off <<= 1) {
            int t = __shfl_up_sync(0xffffffffu, lb, off);
            if (lane >= off) lb += t;
        }
        lb -= run;                             // exclusive
        #pragma unroll
        for (int j = 0; j < 8; j++) {
            int idx = lane * 8 + j;
            sbase[idx >> 7][e][idx & 127] = lb + pre[j];
        }
    }
    __syncthreads();

    // Stage 3: placement (parallel across all 256 (phase,chunk) threads)
    {
        int run[E_NUM];
        #pragma unroll
        for (int e = 0; e < E_NUM; e++) run[e] = 0;
        #pragma unroll 4
        for (int j = 0; j < 32; j++) {
            int s = chunk * 32 + j;
            int e = stopk[s * 2 + p];
            e = (e < 0) ? 0 : ((e > 7) ? 7 : e);
            int r = 0;
            #pragma unroll
            for (int ee = 0; ee < E_NUM; ee++) {
                if (e == ee) r = run[ee]++;
            }
            int loc = sbase[p][e][chunk] + r;
            bool valid = loc < C_CAP;
            int flat = e * C_CAP + (valid ? loc : (C_CAP - 1));
            d_flat[s * 2 + p] = flat;
            if (valid) d_perm[flat] = s;
            else       d_gate[s * 2 + p] = 0.f;
        }
    }

    // Stage 4: me[e] = sum_s scores[s][e] — warp w owns expert w, fixed-order shfl reduce
    {
        const int e = wid;
        float acc = 0.f;
        for (int s = lane; s < S_TOK; s += 32)
            acc += d_scores[s * E_NUM + e];
        #pragma unroll
        for (int off = 16; off; off >>= 1)
            acc += __shfl_down_sync(0xffffffffu, acc, off);
        if (lane == 0) d_me[e] = acc;
    }
}

// -------- tf32 GEMM, block 128x256, 256 threads / 8 warps (warp 64x64), 3-stage cp.async --------
// (R14 configuration, verified wait semantics: prologue commits 2 groups; CP_WAIT(1) at iter
//  it leaves group it+1 outstanding and completes group it.)
#define ROWB_A 144
#define ROWN_B 1056
#define OFF_B  18432              // 128 * 144
#define STAGE_B 52224             // 18432 + 32*1056
template <int PHASE>
__global__ __launch_bounds__(256) void gemm_mma() {
    constexpr int KSEG = (PHASE == 1) ? M_DIM : H_DIM;
    constexpr int NDIM = (PHASE == 1) ? H_DIM : M_DIM;
    constexpr int TPS = KSEG / 32;

    extern __shared__ __align__(16) char smem[];
    __shared__ int sRow[128];

    const int tid = threadIdx.x;
    const int lane = tid & 31;
    const int wid = tid >> 5;
    const int wm = wid >> 2;        // 0..1  (64-row slice)
    const int wn = wid & 3;         // 0..3  (64-col slice)
    const int e = blockIdx.z;
    const int M0 = blockIdx.y * 128;
    const int N0 = blockIdx.x * 256;
    const uint32_t sbase = smem_u32(smem);

    if (PHASE == 1) {
        if (tid < 128) sRow[tid] = d_perm[e * C_CAP + tid + M0];
    }
    __syncthreads();

    const float* A = (PHASE == 1) ? d_xr : d_h;        // pre-rounded tf32
    const float* W = (PHASE == 1) ? g_fc1w : g_fc2w;   // [e][k][n], raw fp32

    auto issue_stage = [&](int stg, int kt) {
        const int kb = kt * 32;
        uint32_t base = sbase + stg * STAGE_B;
        #pragma unroll
        for (int i = 0; i < 4; i++) {       // A: 128 rows x 8 chunks(16B)
            int ch = tid + i * 256, r = ch >> 3, c = ch & 7;
            size_t srcoff;
            int bytes = 16;
            if (PHASE == 1) {
                int sr = sRow[r];
                srcoff = (sr >= 0) ? ((size_t)sr * KSEG + kb + c * 4) : 0;
                if (sr < 0) bytes = 0;
            } else {
                srcoff = (size_t)(e * C_CAP + M0 + r) * KSEG + kb + c * 4;
            }
            cpa16(base + r * ROWB_A + c * 16, A + srcoff, bytes);
        }
        #pragma unroll
        for (int i = 0; i < 8; i++) {       // B: 32 k-rows x 64 chunks(16B)
            int ch = tid + i * 256, r = ch >> 6, c = ch & 63;
            size_t srcoff = (size_t)e * KSEG * NDIM + (size_t)(kb + r) * NDIM + N0 + c * 4;
            cpa16(base + OFF_B + r * ROWN_B + c * 16, W + srcoff, 16);
        }
    };

    float acc[4][8][4];
    #pragma unroll
    for (int mi = 0; mi < 4; mi++)
        #pragma unroll
        for (int ni = 0; ni < 8; ni++)
            #pragma unroll
            for (int q = 0; q < 4; q++) acc[mi][ni][q] = 0.f;

    const int l_r = lane & 15;
    const int l_c = (lane >> 4) * 16;
    const int bq = lane >> 2;       // n offset within n8 block
    const int br = lane & 3;        // k offset within k8 block

    issue_stage(0, 0);
    CP_COMMIT();
    issue_stage(1, 1);
    CP_COMMIT();

    for (int it = 0; it < TPS; it++) {
        if (it + 1 < TPS) CP_WAIT(1);
        else              CP_WAIT(0);
        __syncthreads();

        if (it + 2 < TPS) { issue_stage((it + 2) % 3, it + 2); CP_COMMIT(); }

        uint32_t base = sbase + (it % 3) * STAGE_B;
        #pragma unroll
        for (int kk = 0; kk < 4; kk++) {    // four k8 steps per k32 stage
            uint32_t af[4][4];
            #pragma unroll
            for (int mi = 0; mi < 4; mi++) {
                uint32_t ad = base + (uint32_t)(wm * 64 + mi * 16 + l_r) * ROWB_A
                            + (uint32_t)(kk * 32 + l_c);
                LDSM4(af[mi][0], af[mi][1], af[mi][2], af[mi][3], ad);
            }
            uint32_t bd0 = base + OFF_B + (uint32_t)(kk * 8 + br) * ROWN_B
                         + (uint32_t)(wn * 64 + bq) * 4;
            uint32_t bfr[8][2];
            #pragma unroll
            for (int ni = 0; ni < 8; ni++) {
                bfr[ni][0] = lds_tf32(bd0 + ni * 32);
                bfr[ni][1] = lds_tf32(bd0 + ni * 32 + 4 * ROWN_B);
            }
            #pragma unroll
            for (int mi = 0; mi < 4; mi++)
                #pragma unroll
                for (int ni = 0; ni < 8; ni++)
                    MMA16808(acc[mi][ni], af[mi], bfr[ni][0], bfr[ni][1]);
        }
    }

    // ---- epilogue ----
    const float* bias = (PHASE == 1) ? g_fc1b : g_fc2b;
    #pragma unroll
    for (int mi = 0; mi < 4; mi++) {
        #pragma unroll
        for (int ni = 0; ni < 8; ni++) {
            int c = N0 + wn * 64 + ni * 8 + (lane & 3) * 2;
            float2 bv = *(const float2*)&bias[(size_t)e * NDIM + c];
            int r0 = M0 + wm * 64 + mi * 16 + (lane >> 2);
            #pragma unroll
            for (int h = 0; h < 2; h++) {
                int rg = r0 + h * 8;
                float v0 = acc[mi][ni][h * 2 + 0] + bv.x;
                float v1 = acc[mi][ni][h * 2 + 1] + bv.y;
                if (PHASE == 1) {
                    v0 = fmaxf(v0, 0.f);
                    v1 = fmaxf(v1, 0.f);
                    uint2 t = make_uint2(to_tf32(v0), to_tf32(v1));
                    size_t o = (size_t)(e * C_CAP + rg) * H_DIM + c;
                    *(uint2*)(d_h + o) = t;
                } else {
                    size_t o = (size_t)(e * C_CAP + rg) * M_DIM + c;
                    *(float2*)(d_yo + o) = make_float2(v0, v1);
                }
            }
        }
    }
}

// ---------------- combine ----------------
__global__ __launch_bounds__(256) void combine_kernel(float* __restrict__ out) {
    int s = blockIdx.x;
    int tid = threadIdx.x;
    int f0 = d_flat[s * 2 + 0];
    int f1 = d_flat[s * 2 + 1];
    float g0 = d_gate[s * 2 + 0];
    float g1 = d_gate[s * 2 + 1];
    float4 a = ((const float4*)(d_yo + (size_t)f0 * M_DIM))[tid];
    float4 b = ((const float4*)(d_yo + (size_t)f1 * M_DIM))[tid];
    float4 o;
    o.x = g0 * a.x + g1 * b.x;
    o.y = g0 * a.y + g1 * b.y;
    o.z = g0 * a.z + g1 * b.z;
    o.w = g0 * a.w + g1 * b.w;
    ((float4*)(out + (size_t)s * M_DIM))[tid] = o;
}

// ---------------- l_aux ----------------
__global__ __launch_bounds__(32) void laux_kernel(float* __restrict__ out, int write) {
    if (threadIdx.x == 0 && write) {
        float l = 0.f;
        for (int e = 0; e < E_NUM; e++)
            l += (d_me[e] / (float)S_TOK) * ((float)d_ce[e] / (float)S_TOK);
        out[(size_t)S_TOK * M_DIM] = l * (float)E_NUM;
    }
}

// ---------------- launch ----------------
extern "C" void kernel_launch(void* const* d_in, const int* in_sizes, int n_in,
                              void* d_out, int out_size) {
    long long mx = 0;
    for (int i = 0; i < n_in; i++) if ((long long)in_sizes[i] > mx) mx = in_sizes[i];
    long long div = (mx >= 134217728LL) ? 4 : 1;

    const float *x = 0, *fc1_b = 0;
    const float* big[2] = {0, 0};
    const float* sml[2] = {0, 0};
    int nbig = 0, nsml = 0;
    for (int i = 0; i < n_in; i++) {
        const float* p = (const float*)d_in[i];
        long long n = (long long)in_sizes[i] / div;
        if (n == (long long)S_TOK * M_DIM) x = p;
        else if (n == (long long)E_NUM * H_DIM) fc1_b = p;
        else if (n == (long long)E_NUM * M_DIM * H_DIM) { if (nbig < 2) big[nbig++] = p; }
        else if (n == (long long)M_DIM * E_NUM) { if (nsml < 2) sml[nsml++] = p; }
    }
    if (!x || !fc1_b || nbig < 2 || nsml < 2) {
        x = (const float*)d_in[0];
        sml[0] = (const float*)d_in[1];
        big[0] = (const float*)d_in[2];
        fc1_b = (const float*)d_in[3];
        big[1] = (const float*)d_in[4];
        sml[1] = (const float*)d_in[5];
    }
    float* out = (float*)d_out;

    const int SMEM_DYN = 3 * STAGE_B;  // 156672 B
    cudaFuncSetAttribute(gemm_mma<1>, cudaFuncAttributeMaxDynamicSharedMemorySize, SMEM_DYN);
    cudaFuncSetAttribute(gemm_mma<2>, cudaFuncAttributeMaxDynamicSharedMemorySize, SMEM_DYN);

    select_kernel<<<1, 32>>>(x, fc1_b, sml[0], sml[1], big[0], big[1]);
    round_x_kernel<<<(S_TOK * M_DIM) / 4 / 256, 256>>>();
    gate_kernel<<<S_TOK / 8, 256>>>();
    route_kernel<<<1, 256>>>();          // also computes d_me (fused, order-fixed)

    {
        dim3 g(H_DIM / 256, C_CAP / 128, E_NUM);  // (16, 8, 8)
        gemm_mma<1><<<g, 256, SMEM_DYN>>>();
    }
    {
        dim3 g(M_DIM / 256, C_CAP / 128, E_NUM);  // (4, 8, 8)
        gemm_mma<2><<<g, 256, SMEM_DYN>>>();
    }

    combine_kernel<<<S_TOK, 256>>>(out);
    laux_kernel<<<1, 32>>>(out, out_size > S_TOK * M_DIM ? 1 : 0);
}

// round 17
// speedup vs baseline: 1.0652x; 1.0190x over previous
#include <cuda_runtime.h>
#include <cuda_bf16.h>
#include <math.h>
#include <stdint.h>

#define S_TOK 4096
#define M_DIM 1024
#define H_DIM 4096
#define E_NUM 8
#define C_CAP 1024
#define KTOP  2

// ---------------- scratch (__device__ globals; referenced ONLY from device code) ----------------
__device__ float d_xr[(size_t)S_TOK * M_DIM];                 // tf32-rounded x
__device__ float d_h[(size_t)E_NUM * C_CAP * H_DIM];          // tf32-rounded activations
__device__ float d_yo[(size_t)E_NUM * C_CAP * M_DIM];
__device__ float d_scores[S_TOK * E_NUM];
__device__ int   d_topk[S_TOK * KTOP];
__device__ float d_gate[S_TOK * KTOP];
__device__ int   d_flat[S_TOK * KTOP];
__device__ int   d_perm[E_NUM * C_CAP];
__device__ float d_me[E_NUM];
__device__ int   d_ce[E_NUM];

__device__ const float* g_x;
__device__ const float* g_wg;
__device__ const float* g_fc1w;
__device__ const float* g_fc1b;
__device__ const float* g_fc2w;
__device__ const float* g_fc2b;

// ---------------- generic-PTX helpers (sm_80+; valid on compute_103) ----------------
__device__ __forceinline__ uint32_t smem_u32(const void* p) {
    uint32_t a;
    asm("{ .reg .u64 t; cvta.to.shared.u64 t, %1; cvt.u32.u64 %0, t; }" : "=r"(a) : "l"(p));
    return a;
}
__device__ __forceinline__ void cpa16(uint32_t dst, const void* src, int src_bytes) {
    asm volatile("cp.async.cg.shared.global [%0], [%1], 16, %2;"
                 :: "r"(dst), "l"(src), "r"(src_bytes) : "memory");
}
#define CP_COMMIT() asm volatile("cp.async.commit_group;" ::: "memory")
#define CP_WAIT(n)  asm volatile("cp.async.wait_group %0;" :: "n"(n) : "memory")
#define LDSM4(r0, r1, r2, r3, addr)                                        \
    asm volatile("ldmatrix.sync.aligned.m8n8.x4.shared.b16 {%0,%1,%2,%3}, [%4];" \
                 : "=r"(r0), "=r"(r1), "=r"(r2), "=r"(r3) : "r"(addr))
#define MMA16808(d, a, b0, b1)                                             \
    asm volatile("mma.sync.aligned.m16n8k8.row.col.f32.tf32.tf32.f32 "     \
                 "{%0,%1,%2,%3}, {%4,%5,%6,%7}, {%8,%9}, {%0,%1,%2,%3};"   \
                 : "+f"((d)[0]), "+f"((d)[1]), "+f"((d)[2]), "+f"((d)[3])  \
                 : "r"((a)[0]), "r"((a)[1]), "r"((a)[2]), "r"((a)[3]),     \
                   "r"(b0), "r"(b1))
__device__ __forceinline__ uint32_t to_tf32(float v) {
    uint32_t r;
    asm("cvt.rna.tf32.f32 %0, %1;" : "=r"(r) : "f"(v));
    return r;
}
__device__ __forceinline__ uint32_t lds_tf32(uint32_t addr) {
    float v;
    asm volatile("ld.shared.f32 %0, [%1];" : "=f"(v) : "r"(addr));
    return to_tf32(v);
}

// ---------------- select: resolve ambiguous inputs by content ----------------
__global__ __launch_bounds__(32) void select_kernel(
    const float* x, const float* fc1b,
    const float* s0, const float* s1,
    const float* b0, const float* b1) {
    int lane = threadIdx.x;
    float sa = 0.f, sb = 0.f, ca = 0.f, cb = 0.f;
    for (int i = lane; i < 8192; i += 32) {
        sa += fabsf(s0[i]);
        sb += fabsf(s1[i]);
        ca += fabsf(b0[i]);
        cb += fabsf(b1[i]);
    }
    #pragma unroll
    for (int off = 16; off; off >>= 1) {
        sa += __shfl_down_sync(0xffffffffu, sa, off);
        sb += __shfl_down_sync(0xffffffffu, sb, off);
        ca += __shfl_down_sync(0xffffffffu, ca, off);
        cb += __shfl_down_sync(0xffffffffu, cb, off);
    }
    if (lane == 0) {
        g_x = x;
        g_fc1b = fc1b;
        if (sa >= sb) { g_wg = s0; g_fc2b = s1; }
        else          { g_wg = s1; g_fc2b = s0; }
        if (ca >= cb) { g_fc1w = b0; g_fc2w = b1; }
        else          { g_fc1w = b1; g_fc2w = b0; }
        for (int e = 0; e < E_NUM; e++) d_ce[e] = 0;
    }
}

// ---------------- round x to tf32 (vectorized) ----------------
__global__ __launch_bounds__(256) void round_x_kernel() {
    size_t i4 = (size_t)blockIdx.x * 256 + threadIdx.x;
    float4 v = ((const float4*)g_x)[i4];
    uint4 o;
    o.x = to_tf32(v.x);
    o.y = to_tf32(v.y);
    o.z = to_tf32(v.z);
    o.w = to_tf32(v.w);
    ((uint4*)d_xr)[i4] = o;
}

// ---------------- gating: one warp per token ----------------
__global__ __launch_bounds__(256) void gate_kernel() {
    const int warp = threadIdx.x >> 5;
    const int lane = threadIdx.x & 31;
    const int s = blockIdx.x * 8 + warp;
    if (s >= S_TOK) return;
    const float* x = g_x;
    const float* wg = g_wg;

    float acc[E_NUM] = {0.f, 0.f, 0.f, 0.f, 0.f, 0.f, 0.f, 0.f};
    const float* xrow = x + (size_t)s * M_DIM;
    for (int k = lane; k < M_DIM; k += 32) {
        float xv = xrow[k];
        const float4* w = (const float4*)(wg + (size_t)k * E_NUM);
        float4 w0 = w[0], w1 = w[1];
        acc[0] += xv * w0.x; acc[1] += xv * w0.y; acc[2] += xv * w0.z; acc[3] += xv * w0.w;
        acc[4] += xv * w1.x; acc[5] += xv * w1.y; acc[6] += xv * w1.z; acc[7] += xv * w1.w;
    }
    #pragma unroll
    for (int off = 16; off; off >>= 1) {
        #pragma unroll
        for (int e = 0; e < E_NUM; e++)
            acc[e] += __shfl_down_sync(0xffffffffu, acc[e], off);
    }
    if (lane == 0) {
        float mx = acc[0];
        #pragma unroll
        for (int e = 1; e < E_NUM; e++) mx = fmaxf(mx, acc[e]);
        float sum = 0.f, sc[E_NUM];
        #pragma unroll
        for (int e = 0; e < E_NUM; e++) { sc[e] = expf(acc[e] - mx); sum += sc[e]; }
        float inv = 1.f / sum;
        #pragma unroll
        for (int e = 0; e < E_NUM; e++) { sc[e] *= inv; d_scores[s * E_NUM + e] = sc[e]; }
        int id0 = 0;
        #pragma unroll
        for (int e = 1; e < E_NUM; e++) if (sc[e] > sc[id0]) id0 = e;
        int id1 = -1;
        float b1 = -1.f;
        #pragma unroll
        for (int e = 0; e < E_NUM; e++) {
            if (e != id0 && sc[e] > b1) { b1 = sc[e]; id1 = e; }
        }
        if (id1 < 0) id1 = (id0 + 1) & 7;
        float v0 = sc[id0], v1 = sc[id1];
        float denom = fmaxf(v0 + v1, 1e-7f);
        d_topk[s * 2 + 0] = id0;
        d_topk[s * 2 + 1] = id1;
        d_gate[s * 2 + 0] = v0 / denom;
        d_gate[s * 2 + 1] = v1 / denom;
        atomicAdd(&d_ce[id0], 1);
    }
}

// ---- routing (two-level scan) + me reduction fused; token-ordered, deterministic ----
#define NCHUNK 128   // 4096 tokens / 32 per chunk
__global__ __launch_bounds__(256) void route_kernel() {
    const int tid = threadIdx.x;
    const int lane = tid & 31;
    const int wid = tid >> 5;
    __shared__ int stopk[S_TOK * KTOP];              // 32 KB
    __shared__ int scnt[KTOP][E_NUM][NCHUNK];        // 8 KB
    __shared__ int sbase[KTOP][E_NUM][NCHUNK];       // 8 KB

    for (int i = tid; i < E_NUM * C_CAP; i += 256) d_perm[i] = -1;
    for (int i = tid; i < S_TOK * KTOP; i += 256) stopk[i] = d_topk[i];
    __syncthreads();

    const int p = tid >> 7;           // phase 0/1
    const int chunk = tid & 127;      // 32-token chunk
    {
        int cnt[E_NUM];
        #pragma unroll
        for (int e = 0; e < E_NUM; e++) cnt[e] = 0;
        #pragma unroll 4
        for (int j = 0; j < 32; j++) {
            int e = stopk[(chunk * 32 + j) * 2 + p];
            e = (e < 0) ? 0 : ((e > 7) ? 7 : e);
            #pragma unroll
            for (int ee = 0; ee < E_NUM; ee++) cnt[ee] += (e == ee);
        }
        #pragma unroll
        for (int e = 0; e < E_NUM; e++) scnt[p][e][chunk] = cnt[e];
    }
    __syncthreads();

    {
        const int e = wid;
        int v[8], pre[8], run = 0;
        #pragma unroll
        for (int j = 0; j < 8; j++) {
            int idx = lane * 8 + j;
            v[j] = scnt[idx >> 7][e][idx & 127];
            pre[j] = run;
            run += v[j];
        }
        int lb = run;
        #pragma unroll
        for (int off = 1; off < 32; off <<= 1) {
            int t = __shfl_up_sync(0xffffffffu, lb, off);
            if (lane >= off) lb += t;
        }
        lb -= run;
        #pragma unroll
        for (int j = 0; j < 8; j++) {
            int idx = lane * 8 + j;
            sbase[idx >> 7][e][idx & 127] = lb + pre[j];
        }
    }
    __syncthreads();

    {
        int run[E_NUM];
        #pragma unroll
        for (int e = 0; e < E_NUM; e++) run[e] = 0;
        #pragma unroll 4
        for (int j = 0; j < 32; j++) {
            int s = chunk * 32 + j;
            int e = stopk[s * 2 + p];
            e = (e < 0) ? 0 : ((e > 7) ? 7 : e);
            int r = 0;
            #pragma unroll
            for (int ee = 0; ee < E_NUM; ee++) {
                if (e == ee) r = run[ee]++;
            }
            int loc = sbase[p][e][chunk] + r;
            bool valid = loc < C_CAP;
            int flat = e * C_CAP + (valid ? loc : (C_CAP - 1));
            d_flat[s * 2 + p] = flat;
            if (valid) d_perm[flat] = s;
            else       d_gate[s * 2 + p] = 0.f;
        }
    }

    // me[e]: warp w owns expert w, fixed-order shfl reduce
    {
        const int e = wid;
        float acc = 0.f;
        for (int s = lane; s < S_TOK; s += 32)
            acc += d_scores[s * E_NUM + e];
        #pragma unroll
        for (int off = 16; off; off >>= 1)
            acc += __shfl_down_sync(0xffffffffu, acc, off);
        if (lane == 0) d_me[e] = acc;
    }
}

// -------- tf32 GEMM, block 128x128, 128 threads / 4 warps (warp 64x64), 3-stage cp.async --------
// 2 CTAs/SM (regs 164*128*2=42K, smem 2*107520=215KB): independent barriers de-correlate
// pipeline stalls, feeding the tensor pipe from two CTAs per SMSP.
#define ROWB_A 144
#define ROWN_B 544                // (128 + 8 pad) * 4B
#define OFF_B  18432              // 128 * 144
#define STAGE_B 35840             // 18432 + 32*544
template <int PHASE>
__global__ __launch_bounds__(128, 2) void gemm_mma() {
    constexpr int KSEG = (PHASE == 1) ? M_DIM : H_DIM;
    constexpr int NDIM = (PHASE == 1) ? H_DIM : M_DIM;
    constexpr int TPS = KSEG / 32;

    extern __shared__ __align__(16) char smem[];
    __shared__ int sRow[128];

    const int tid = threadIdx.x;
    const int lane = tid & 31;
    const int wid = tid >> 5;       // 0..3
    const int wm = wid >> 1;        // 0..1  (64-row slice)
    const int wn = wid & 1;         // 0..1  (64-col slice)
    const int e = blockIdx.z;
    const int M0 = blockIdx.y * 128;
    const int N0 = blockIdx.x * 128;
    const uint32_t sbase = smem_u32(smem);

    if (PHASE == 1) {
        sRow[tid] = d_perm[e * C_CAP + tid + M0];   // 128 threads cover 128 rows
    }
    __syncthreads();

    const float* A = (PHASE == 1) ? d_xr : d_h;        // pre-rounded tf32
    const float* W = (PHASE == 1) ? g_fc1w : g_fc2w;   // [e][k][n], raw fp32

    auto issue_stage = [&](int stg, int kt) {
        const int kb = kt * 32;
        uint32_t base = sbase + stg * STAGE_B;
        #pragma unroll
        for (int i = 0; i < 8; i++) {       // A: 128 rows x 8 chunks(16B) = 1024
            int ch = tid + i * 128, r = ch >> 3, c = ch & 7;
            size_t srcoff;
            int bytes = 16;
            if (PHASE == 1) {
                int sr = sRow[r];
                srcoff = (sr >= 0) ? ((size_t)sr * KSEG + kb + c * 4) : 0;
                if (sr < 0) bytes = 0;
            } else {
                srcoff = (size_t)(e * C_CAP + M0 + r) * KSEG + kb + c * 4;
            }
            cpa16(base + r * ROWB_A + c * 16, A + srcoff, bytes);
        }
        #pragma unroll
        for (int i = 0; i < 8; i++) {       // B: 32 k-rows x 32 chunks(16B) = 1024
            int ch = tid + i * 128, r = ch >> 5, c = ch & 31;
            size_t srcoff = (size_t)e * KSEG * NDIM + (size_t)(kb + r) * NDIM + N0 + c * 4;
            cpa16(base + OFF_B + r * ROWN_B + c * 16, W + srcoff, 16);
        }
    };

    float acc[4][8][4];
    #pragma unroll
    for (int mi = 0; mi < 4; mi++)
        #pragma unroll
        for (int ni = 0; ni < 8; ni++)
            #pragma unroll
            for (int q = 0; q < 4; q++) acc[mi][ni][q] = 0.f;

    const int l_r = lane & 15;
    const int l_c = (lane >> 4) * 16;
    const int bq = lane >> 2;       // n offset within n8 block
    const int br = lane & 3;        // k offset within k8 block

    issue_stage(0, 0);
    CP_COMMIT();
    issue_stage(1, 1);
    CP_COMMIT();

    for (int it = 0; it < TPS; it++) {
        if (it + 1 < TPS) CP_WAIT(1);
        else              CP_WAIT(0);
        __syncthreads();

        if (it + 2 < TPS) { issue_stage((it + 2) % 3, it + 2); CP_COMMIT(); }

        uint32_t base = sbase + (it % 3) * STAGE_B;
        #pragma unroll
        for (int kk = 0; kk < 4; kk++) {    // four k8 steps per k32 stage
            uint32_t af[4][4];
            #pragma unroll
            for (int mi = 0; mi < 4; mi++) {
                uint32_t ad = base + (uint32_t)(wm * 64 + mi * 16 + l_r) * ROWB_A
                            + (uint32_t)(kk * 32 + l_c);
                LDSM4(af[mi][0], af[mi][1], af[mi][2], af[mi][3], ad);
            }
            uint32_t bd0 = base + OFF_B + (uint32_t)(kk * 8 + br) * ROWN_B
                         + (uint32_t)(wn * 64 + bq) * 4;
            uint32_t bfr[8][2];
            #pragma unroll
            for (int ni = 0; ni < 8; ni++) {
                bfr[ni][0] = lds_tf32(bd0 + ni * 32);
                bfr[ni][1] = lds_tf32(bd0 + ni * 32 + 4 * ROWN_B);
            }
            #pragma unroll
            for (int mi = 0; mi < 4; mi++)
                #pragma unroll
                for (int ni = 0; ni < 8; ni++)
                    MMA16808(acc[mi][ni], af[mi], bfr[ni][0], bfr[ni][1]);
        }
    }

    // ---- epilogue ----
    const float* bias = (PHASE == 1) ? g_fc1b : g_fc2b;
    #pragma unroll
    for (int mi = 0; mi < 4; mi++) {
        #pragma unroll
        for (int ni = 0; ni < 8; ni++) {
            int c = N0 + wn * 64 + ni * 8 + (lane & 3) * 2;
            float2 bv = *(const float2*)&bias[(size_t)e * NDIM + c];
            int r0 = M0 + wm * 64 + mi * 16 + (lane >> 2);
            #pragma unroll
            for (int h = 0; h < 2; h++) {
                int rg = r0 + h * 8;
                float v0 = acc[mi][ni][h * 2 + 0] + bv.x;
                float v1 = acc[mi][ni][h * 2 + 1] + bv.y;
                if (PHASE == 1) {
                    v0 = fmaxf(v0, 0.f);
                    v1 = fmaxf(v1, 0.f);
                    uint2 t = make_uint2(to_tf32(v0), to_tf32(v1));
                    size_t o = (size_t)(e * C_CAP + rg) * H_DIM + c;
                    *(uint2*)(d_h + o) = t;
                } else {
                    size_t o = (size_t)(e * C_CAP + rg) * M_DIM + c;
                    *(float2*)(d_yo + o) = make_float2(v0, v1);
                }
            }
        }
    }
}

// ---------------- combine ----------------
__global__ __launch_bounds__(256) void combine_kernel(float* __restrict__ out) {
    int s = blockIdx.x;
    int tid = threadIdx.x;
    int f0 = d_flat[s * 2 + 0];
    int f1 = d_flat[s * 2 + 1];
    float g0 = d_gate[s * 2 + 0];
    float g1 = d_gate[s * 2 + 1];
    float4 a = ((const float4*)(d_yo + (size_t)f0 * M_DIM))[tid];
    float4 b = ((const float4*)(d_yo + (size_t)f1 * M_DIM))[tid];
    float4 o;
    o.x = g0 * a.x + g1 * b.x;
    o.y = g0 * a.y + g1 * b.y;
    o.z = g0 * a.z + g1 * b.z;
    o.w = g0 * a.w + g1 * b.w;
    ((float4*)(out + (size_t)s * M_DIM))[tid] = o;
}

// ---------------- l_aux ----------------
__global__ __launch_bounds__(32) void laux_kernel(float* __restrict__ out, int write) {
    if (threadIdx.x == 0 && write) {
        float l = 0.f;
        for (int e = 0; e < E_NUM; e++)
            l += (d_me[e] / (float)S_TOK) * ((float)d_ce[e] / (float)S_TOK);
        out[(size_t)S_TOK * M_DIM] = l * (float)E_NUM;
    }
}

// ---------------- launch ----------------
extern "C" void kernel_launch(void* const* d_in, const int* in_sizes, int n_in,
                              void* d_out, int out_size) {
    long long mx = 0;
    for (int i = 0; i < n_in; i++) if ((long long)in_sizes[i] > mx) mx = in_sizes[i];
    long long div = (mx >= 134217728LL) ? 4 : 1;

    const float *x = 0, *fc1_b = 0;
    const float* big[2] = {0, 0};
    const float* sml[2] = {0, 0};
    int nbig = 0, nsml = 0;
    for (int i = 0; i < n_in; i++) {
        const float* p = (const float*)d_in[i];
        long long n = (long long)in_sizes[i] / div;
        if (n == (long long)S_TOK * M_DIM) x = p;
        else if (n == (long long)E_NUM * H_DIM) fc1_b = p;
        else if (n == (long long)E_NUM * M_DIM * H_DIM) { if (nbig < 2) big[nbig++] = p; }
        else if (n == (long long)M_DIM * E_NUM) { if (nsml < 2) sml[nsml++] = p; }
    }
    if (!x || !fc1_b || nbig < 2 || nsml < 2) {
        x = (const float*)d_in[0];
        sml[0] = (const float*)d_in[1];
        big[0] = (const float*)d_in[2];
        fc1_b = (const float*)d_in[3];
        big[1] = (const float*)d_in[4];
        sml[1] = (const float*)d_in[5];
    }
    float* out = (float*)d_out;

    const int SMEM_DYN = 3 * STAGE_B;  // 107520 B -> 2 CTAs/SM
    cudaFuncSetAttribute(gemm_mma<1>, cudaFuncAttributeMaxDynamicSharedMemorySize, SMEM_DYN);
    cudaFuncSetAttribute(gemm_mma<2>, cudaFuncAttributeMaxDynamicSharedMemorySize, SMEM_DYN);

    select_kernel<<<1, 32>>>(x, fc1_b, sml[0], sml[1], big[0], big[1]);
    round_x_kernel<<<(S_TOK * M_DIM) / 4 / 256, 256>>>();
    gate_kernel<<<S_TOK / 8, 256>>>();
    route_kernel<<<1, 256>>>();          // also computes d_me (fused, order-fixed)

    {
        dim3 g(H_DIM / 128, C_CAP / 128, E_NUM);  // (32, 8, 8) = 2048 CTAs
        gemm_mma<1><<<g, 128, SMEM_DYN>>>();
    }
    {
        dim3 g(M_DIM / 128, C_CAP / 128, E_NUM);  // (8, 8, 8) = 512 CTAs
        gemm_mma<2><<<g, 128, SMEM_DYN>>>();
    }

    combine_kernel<<<S_TOK, 256>>>(out);
    laux_kernel<<<1, 32>>>(out, out_size > S_TOK * M_DIM ? 1 : 0);
}